// round 8
// baseline (speedup 1.0000x reference)
#include <cuda_runtime.h>
#include <cuda_bf16.h>

// Two-kernel + PDL (proven 16.9us). This round: the per-endpoint scatter
// payload is packed into ONE red.global.add.u64 (vs red.v4.f32 = 4 words).
// Fixed-point fields, no cross-field carry possible:
//   [63:56] z   (zero-length slot count,   max deg ~45 << 255)
//   [55:48] m   (unit slot count)
//   [47:24] Cfix = sum round((cos4t+1)*8192)   <= 255*16385 < 2^24
//   [23: 0] Sfix = sum round((sin4t+1)*8192)
// Decode: C = Cfix/8192 - m, S = Sfix/8192 - m, deg = m + z.
// Closed form: per-node pair sum = (m^2 - C^2 - S^2)/16;
// P = sum deg(deg-1)/2; loss = sum(...)/(16*P). Quantization error ~4e-8 global.
// State self-cleans each run (graph-replay safe).

#define MAXN 65536

__device__ unsigned long long g_acc[MAXN];
__device__ double g_num;
__device__ double g_pairs;
__device__ unsigned g_done;

__device__ __forceinline__ void red_u64(unsigned long long* addr, unsigned long long v) {
    asm volatile("red.global.add.u64 [%0], %1;"
                 :: "l"(addr), "l"(v) : "memory");
}

__global__ void edge_kernel(const float2* __restrict__ pos,
                            const int* __restrict__ src,
                            const int* __restrict__ dst,
                            int E) {
    int e = blockIdx.x * blockDim.x + threadIdx.x;
    if (e < E) {
        int a = src[e];
        int b = dst[e];
        float2 pa = __ldg(pos + a);
        float2 pb = __ldg(pos + b);
        float dx = pb.x - pa.x;
        float dy = pb.y - pa.y;
        float n2 = dx * dx + dy * dy;

        unsigned long long payload;
        if (n2 > 0.f) {
            float inv = rsqrtf(n2);
            float c = dx * inv, s = dy * inv;
            float c2 = c * c - s * s;
            float s2 = 2.f * c * s;
            float c4 = c2 * c2 - s2 * s2;
            float s4 = 2.f * c2 * s2;
            unsigned cf = __float2uint_rn(fmaxf((c4 + 1.f) * 8192.f, 0.f));
            unsigned sf = __float2uint_rn(fmaxf((s4 + 1.f) * 8192.f, 0.f));
            payload = (1ULL << 48) | ((unsigned long long)cf << 24) | sf;
        } else {
            payload = 1ULL << 56;   // zero-length slot: z += 1
        }
        red_u64(&g_acc[a], payload);
        red_u64(&g_acc[b], payload);
    }
#if __CUDA_ARCH__ >= 900
    cudaTriggerProgrammaticLaunchCompletion();
#endif
}

__global__ void reduce_finalize_kernel(float* __restrict__ out, int n) {
#if __CUDA_ARCH__ >= 900
    cudaGridDependencySynchronize();   // edge_kernel results now visible
#endif
    int i = blockIdx.x * blockDim.x + threadIdx.x;
    float num = 0.f, p = 0.f;
    if (i < n) {
        unsigned long long v = g_acc[i];
        g_acc[i] = 0ULL;                       // self-clean for replay
        float S = (float)(v & 0xFFFFFFULL) * (1.f / 8192.f);
        float C = (float)((v >> 24) & 0xFFFFFFULL) * (1.f / 8192.f);
        float m = (float)((v >> 48) & 0xFFULL);
        float z = (float)(v >> 56);
        C -= m;                                 // remove +1 bias per unit slot
        S -= m;
        num = m * m - C * C - S * S;
        float deg = m + z;
        p = 0.5f * deg * (deg - 1.f);
    }

    // fp32 warp reduce
    #pragma unroll
    for (int off = 16; off > 0; off >>= 1) {
        num += __shfl_down_sync(0xffffffffu, num, off);
        p   += __shfl_down_sync(0xffffffffu, p, off);
    }

    __shared__ double sh_num[8];
    __shared__ double sh_p[8];
    int lane = threadIdx.x & 31;
    int wid  = threadIdx.x >> 5;
    if (lane == 0) { sh_num[wid] = (double)num; sh_p[wid] = (double)p; }
    __syncthreads();

    if (wid == 0) {
        double dnum = (lane < 8) ? sh_num[lane] : 0.0;
        double dp   = (lane < 8) ? sh_p[lane]   : 0.0;
        #pragma unroll
        for (int off = 4; off > 0; off >>= 1) {
            dnum += __shfl_down_sync(0xffffffffu, dnum, off);
            dp   += __shfl_down_sync(0xffffffffu, dp, off);
        }
        if (lane == 0) {
            atomicAdd(&g_num, dnum);
            atomicAdd(&g_pairs, dp);
            __threadfence();
            if (atomicAdd(&g_done, 1u) == gridDim.x - 1) {
                double total_num   = atomicAdd(&g_num, 0.0);
                double total_pairs = atomicAdd(&g_pairs, 0.0);
                double denom = 16.0 * total_pairs;
                out[0] = (denom > 0.0) ? (float)(total_num / denom) : 0.0f;
                g_num = 0.0;
                g_pairs = 0.0;
                g_done = 0u;
                __threadfence();
            }
        }
    }
}

extern "C" void kernel_launch(void* const* d_in, const int* in_sizes, int n_in,
                              void* d_out, int out_size) {
    const float* pos = (const float*)d_in[0];       // (1, N, 2)
    const int* edge_index = (const int*)d_in[2];    // (2, E)
    int N = in_sizes[0] / 2;
    int E = in_sizes[2] / 2;
    const int* src = edge_index;
    const int* dst = edge_index + E;
    float* out = (float*)d_out;

    const int tb = 256;
    edge_kernel<<<(E + tb - 1) / tb, tb>>>((const float2*)pos, src, dst, E);

    // PDL: reduce kernel may begin launching while edge_kernel drains;
    // it grid-dependency-syncs before reading edge results.
    cudaLaunchConfig_t cfg = {};
    cfg.gridDim  = dim3((N + tb - 1) / tb);
    cfg.blockDim = dim3(tb);
    cfg.dynamicSmemBytes = 0;
    cfg.stream = 0;
    cudaLaunchAttribute attr[1];
    attr[0].id = cudaLaunchAttributeProgrammaticStreamSerialization;
    attr[0].val.programmaticStreamSerializationAllowed = 1;
    cfg.attrs = attr;
    cfg.numAttrs = 1;
    cudaLaunchKernelEx(&cfg, reduce_finalize_kernel, out, N);
}